// round 11
// baseline (speedup 1.0000x reference)
#include <cuda_runtime.h>
#include <cuda_fp16.h>
#include <cstdint>

#define BB 64
#define SS 576
#define DD 768
#define CC 200
#define NP 208             // padded class dim
#define MT 128             // s-rows per CTA (5 tiles, last zero-filled)
#define KC 32              // K chunk (elems)
#define NK 24              // 768/32
#define NSB 3              // B stages (A-f32 uses 2)

#define AF32_STRIDE 36     // f32 elems per A stage row (144 B)
#define AH_STRIDE   40     // f16 elems per row (80 B, LDSM conflict-free)
#define BH_STRIDE   40

#define SZ_ASTG  (MT * AF32_STRIDE * 4)                 // 18432 per stage
#define SZ_BSTG  (NP * BH_STRIDE * 2)                   // 16640 per stage
#define OFF_AF32 0
#define OFF_AH   (2 * SZ_ASTG)                          // 36864
#define OFF_BH   (OFF_AH + MT * AH_STRIDE * 2)          // 47104
#define OFF_RS   (OFF_BH + NSB * SZ_BSTG)               // 97024
#define OFF_CS   (OFF_RS + MT * 4)                      // 97536
#define SMEM_TOTAL (OFF_CS + NP * 4)                    // 98368

// fp16 copy of attn_w, zero-padded to NP rows (static scratch, no allocs)
__device__ __half g_whf[NP * DD];

__device__ __forceinline__ uint32_t smem_u32(const void* p) {
    uint32_t a;
    asm("{ .reg .u64 t; cvta.to.shared.u64 t, %1; cvt.u32.u64 %0, t; }" : "=r"(a) : "l"(p));
    return a;
}
__device__ __forceinline__ void cp_async16(uint32_t dst, const void* src) {
    asm volatile("{ .reg .u64 g; cvta.to.global.u64 g, %1; cp.async.cg.shared.global [%0], [g], 16; }"
                 :: "r"(dst), "l"(src) : "memory");
}
// predicated: pred==0 -> zero-fill 16 bytes (src not read)
__device__ __forceinline__ void cp_async16p(uint32_t dst, const void* src, int pred) {
    asm volatile("{ .reg .u64 g; .reg .pred p; .reg .u32 sz;\n"
                 "  setp.ne.u32 p, %2, 0; cvta.to.global.u64 g, %1;\n"
                 "  selp.u32 sz, 16, 0, p;\n"
                 "  cp.async.cg.shared.global [%0], [g], 16, sz; }"
                 :: "r"(dst), "l"(src), "r"(pred) : "memory");
}
#define CP_COMMIT() asm volatile("cp.async.commit_group;" ::: "memory")
#define CP_WAIT1()  asm volatile("cp.async.wait_group 1;" ::: "memory")

#define LDSM4(r0, r1, r2, r3, addr)                                           \
    asm volatile("ldmatrix.sync.aligned.m8n8.x4.shared.b16 {%0,%1,%2,%3}, [%4];" \
        : "=r"(r0), "=r"(r1), "=r"(r2), "=r"(r3) : "r"(addr))
#define LDSM2(r0, r1, addr)                                                   \
    asm volatile("ldmatrix.sync.aligned.m8n8.x2.shared.b16 {%0,%1}, [%2];"    \
        : "=r"(r0), "=r"(r1) : "r"(addr))

#define MMA16(c0, c1, a0, a1, a2, a3, b0, b1)                                 \
    asm volatile("mma.sync.aligned.m16n8k16.row.col.f16.f16.f16.f16 "         \
        "{%0,%1},{%2,%3,%4,%5},{%6,%7},{%0,%1};"                              \
        : "+r"(c0), "+r"(c1)                                                  \
        : "r"(a0), "r"(a1), "r"(a2), "r"(a3), "r"(b0), "r"(b1))

__device__ __forceinline__ float sigf(float x) { return 1.f / (1.f + __expf(-x)); }

// ---------------------------------------------------------------------------
// prep kernel: blocks [0,78): convert attn_w -> g_whf (f16, zero-padded rows)
//              blocks [78,1678): global_scores = class_token @ gc_w^T + gc_b
// ---------------------------------------------------------------------------
__global__ void prep_kernel(const float* __restrict__ aw,
                            const float* __restrict__ ct,
                            const float* __restrict__ gcw,
                            const float* __restrict__ gcb,
                            float* __restrict__ out) {
    int bid = blockIdx.x;
    if (bid < 78) {
        int base = bid * 2048 + threadIdx.x * 8;   // 78*2048 = NP*DD
        #pragma unroll
        for (int i = 0; i < 8; ++i) {
            int idx = base + i;
            int c = idx / DD;
            float v = (c < CC) ? aw[idx] : 0.f;
            g_whf[idx] = __float2half(v);
        }
    } else {
        int W = (bid - 78) * 8 + (threadIdx.x >> 5);   // 0..12799
        int lane = threadIdx.x & 31;
        int b = W & 63;
        int c = W >> 6;                                // 0..199
        const float* x = ct + (size_t)b * DD;
        const float* w = gcw + (size_t)c * DD;
        float acc = 0.f;
        #pragma unroll 4
        for (int d = lane; d < DD; d += 32) acc += x[d] * w[d];
        #pragma unroll
        for (int m = 16; m; m >>= 1) acc += __shfl_xor_sync(0xffffffffu, acc, m);
        if (lane == 0) out[b * CC + c] = acc + gcb[c];
    }
}

// ---------------------------------------------------------------------------
// attn kernel: fused logits = patch @ attn_w^T (f16 mma.sync, cp.async pipe),
//   out[b,c] += lam/(S*D) * sum_s sigmoid(logit + bias) * rowsum[b,s]
// CTA tile M=128 x N=208; warps 4(m) x 2(n); warp tile 32 x 104 (f16 acc).
// A f32 ring: 2 stages (freed at convert). B f16 ring: 3 stages.
// ---------------------------------------------------------------------------
__global__ void __launch_bounds__(256, 2)
attn_kernel(const float* __restrict__ patch,
            const float* __restrict__ attn_b,
            const float* __restrict__ lam,
            float* __restrict__ out) {
    extern __shared__ __align__(16) char smem[];
    float*  Af = (float*)(smem + OFF_AF32);
    __half* Ah = (__half*)(smem + OFF_AH);
    float*  rs = (float*)(smem + OFF_RS);
    float*  colsum = (float*)(smem + OFF_CS);
    const uint32_t sb = smem_u32(smem);

    const int tid  = threadIdx.x;
    const int lane = tid & 31;
    const int warp = tid >> 5;
    const int wm   = warp >> 1;          // 0..3
    const int wn   = warp & 1;           // 0..1
    const int g    = lane >> 2;          // 0..7
    const int q    = lane & 3;           // 0..3

    const int b  = blockIdx.y;
    const int s0 = blockIdx.x * MT;
    const int rows_valid = (SS - s0 < MT) ? (SS - s0) : MT;   // 128 or 64

    if (tid < NP) colsum[tid] = 0.f;

    const float* gA = patch + ((size_t)b * SS + s0) * DD;

    // ldmatrix per-lane byte offsets (conflict-free via 80B row strides)
    const uint32_t aoff = (uint32_t)(((lane & 7) + ((lane >> 3) & 1) * 8) * (AH_STRIDE * 2)
                                     + ((lane >> 4) & 1) * 16);
    const uint32_t boff = (uint32_t)(((lane & 7) + ((lane >> 4) & 1) * 8) * (BH_STRIDE * 2)
                                     + ((lane >> 3) & 1) * 16);
    const uint32_t abase = sb + OFF_AH + wm * 32 * (AH_STRIDE * 2) + aoff;

    uint32_t acc[2][13][2];              // [mfrag][nfrag][c0,c1] f16x2
    #pragma unroll
    for (int mf = 0; mf < 2; ++mf)
        #pragma unroll
        for (int j = 0; j < 13; ++j) { acc[mf][j][0] = 0u; acc[mf][j][1] = 0u; }
    float rsum = 0.f;

    auto issue = [&](int kt) {
        // A: 1024 chunks of 16B, 4 per thread (zero-fill rows >= rows_valid)
        uint32_t adst = sb + OFF_AF32 + (kt & 1) * SZ_ASTG;
        #pragma unroll
        for (int i = 0; i < 4; ++i) {
            int c = tid + 256 * i;
            int row = c >> 3, cc = c & 7;
            cp_async16p(adst + row * (AF32_STRIDE * 4) + cc * 16,
                        gA + (size_t)row * DD + kt * KC + cc * 4,
                        row < rows_valid);
        }
        // B: 832 chunks of 16B
        uint32_t bdst = sb + OFF_BH + (kt % NSB) * SZ_BSTG;
        #pragma unroll
        for (int i = 0; i < 4; ++i) {
            int f = tid + 256 * i;
            if (f < NP * 4) {
                int row = f >> 2, cc = f & 3;
                cp_async16(bdst + row * (BH_STRIDE * 2) + cc * 16,
                           g_whf + (size_t)row * DD + kt * KC + cc * 8);
            }
        }
        CP_COMMIT();
    };

    issue(0);
    issue(1);

    const int crow = tid >> 1;           // convert: 2 threads per row
    const int cseg = tid & 1;            // 16 f32 each

    for (int kt = 0; kt < NK; ++kt) {
        CP_WAIT1();
        __syncthreads();                 // stage kt arrived; prev MMA done with Ah/B

        // ---- convert A f32 -> f16 + rowsum partial (frees A stage kt&1) ----
        {
            const float* ap = Af + (kt & 1) * (MT * AF32_STRIDE)
                            + crow * AF32_STRIDE + cseg * 16;
            float4 x0 = *reinterpret_cast<const float4*>(ap);
            float4 x1 = *reinterpret_cast<const float4*>(ap + 4);
            float4 x2 = *reinterpret_cast<const float4*>(ap + 8);
            float4 x3 = *reinterpret_cast<const float4*>(ap + 12);
            rsum += (x0.x + x0.y) + (x0.z + x0.w) + (x1.x + x1.y) + (x1.z + x1.w)
                  + (x2.x + x2.y) + (x2.z + x2.w) + (x3.x + x3.y) + (x3.z + x3.w);
            __half2 h0 = __floats2half2_rn(x0.x, x0.y);
            __half2 h1 = __floats2half2_rn(x0.z, x0.w);
            __half2 h2 = __floats2half2_rn(x1.x, x1.y);
            __half2 h3 = __floats2half2_rn(x1.z, x1.w);
            __half2 h4 = __floats2half2_rn(x2.x, x2.y);
            __half2 h5 = __floats2half2_rn(x2.z, x2.w);
            __half2 h6 = __floats2half2_rn(x3.x, x3.y);
            __half2 h7 = __floats2half2_rn(x3.z, x3.w);
            uint4 u0, u1;
            u0.x = *reinterpret_cast<uint32_t*>(&h0);
            u0.y = *reinterpret_cast<uint32_t*>(&h1);
            u0.z = *reinterpret_cast<uint32_t*>(&h2);
            u0.w = *reinterpret_cast<uint32_t*>(&h3);
            u1.x = *reinterpret_cast<uint32_t*>(&h4);
            u1.y = *reinterpret_cast<uint32_t*>(&h5);
            u1.z = *reinterpret_cast<uint32_t*>(&h6);
            u1.w = *reinterpret_cast<uint32_t*>(&h7);
            __half* ah = Ah + crow * AH_STRIDE + cseg * 16;
            *reinterpret_cast<uint4*>(ah)     = u0;
            *reinterpret_cast<uint4*>(ah + 8) = u1;
        }
        __syncthreads();                 // Ah visible; A stage (kt&1) fully read

        if (kt + 2 < NK) issue(kt + 2); else CP_COMMIT();

        // ---- mma: 2 k16 halves, 2 mfrags x 13 nfrags ----
        const uint32_t bstage = sb + OFF_BH + (kt % NSB) * SZ_BSTG
                              + wn * 104 * (BH_STRIDE * 2) + boff;
        #pragma unroll
        for (int h = 0; h < 2; ++h) {
            uint32_t a[2][4];
            #pragma unroll
            for (int mf = 0; mf < 2; ++mf)
                LDSM4(a[mf][0], a[mf][1], a[mf][2], a[mf][3],
                      abase + mf * 16 * (AH_STRIDE * 2) + h * 32);
            #pragma unroll
            for (int p = 0; p < 6; ++p) {
                uint32_t b0, b1, b2, b3;
                LDSM4(b0, b1, b2, b3, bstage + p * 16 * (BH_STRIDE * 2) + h * 32);
                #pragma unroll
                for (int mf = 0; mf < 2; ++mf) {
                    MMA16(acc[mf][2 * p][0],     acc[mf][2 * p][1],
                          a[mf][0], a[mf][1], a[mf][2], a[mf][3], b0, b1);
                    MMA16(acc[mf][2 * p + 1][0], acc[mf][2 * p + 1][1],
                          a[mf][0], a[mf][1], a[mf][2], a[mf][3], b2, b3);
                }
            }
            uint32_t b0, b1;
            LDSM2(b0, b1, bstage + 96 * (BH_STRIDE * 2) + h * 32);
            #pragma unroll
            for (int mf = 0; mf < 2; ++mf)
                MMA16(acc[mf][12][0], acc[mf][12][1],
                      a[mf][0], a[mf][1], a[mf][2], a[mf][3], b0, b1);
        }
    }

    // ---- rowsum reduce over the 2 threads per row ----
    rsum += __shfl_xor_sync(0xffffffffu, rsum, 1);
    if ((tid & 1) == 0) rs[crow] = rsum;
    __syncthreads();

    // ---- epilogue: sigmoid(logit + bias) * rowsum, reduce over s ----
    const float r0l = rs[wm * 32 + g];
    const float r0h = rs[wm * 32 + g + 8];
    const float r1l = rs[wm * 32 + 16 + g];
    const float r1h = rs[wm * 32 + 16 + g + 8];
    #pragma unroll
    for (int j = 0; j < 13; ++j) {
        const int ce = wn * 104 + j * 8 + 2 * q;
        float be = (ce     < CC) ? __ldg(&attn_b[ce])     : 0.f;
        float bo = (ce + 1 < CC) ? __ldg(&attn_b[ce + 1]) : 0.f;
        float2 m0a = __half22float2(*reinterpret_cast<__half2*>(&acc[0][j][0]));
        float2 m0b = __half22float2(*reinterpret_cast<__half2*>(&acc[0][j][1]));
        float2 m1a = __half22float2(*reinterpret_cast<__half2*>(&acc[1][j][0]));
        float2 m1b = __half22float2(*reinterpret_cast<__half2*>(&acc[1][j][1]));
        float pe = sigf(m0a.x + be) * r0l + sigf(m0b.x + be) * r0h
                 + sigf(m1a.x + be) * r1l + sigf(m1b.x + be) * r1h;
        float po = sigf(m0a.y + bo) * r0l + sigf(m0b.y + bo) * r0h
                 + sigf(m1a.y + bo) * r1l + sigf(m1b.y + bo) * r1h;
        #pragma unroll
        for (int m = 4; m < 32; m <<= 1) {
            pe += __shfl_xor_sync(0xffffffffu, pe, m);
            po += __shfl_xor_sync(0xffffffffu, po, m);
        }
        if (lane < 4) {                  // lane == q
            atomicAdd(&colsum[ce],     pe);
            atomicAdd(&colsum[ce + 1], po);
        }
    }
    __syncthreads();

    if (tid < CC) {
        float scale = __ldg(&lam[0]) * (1.f / (float)(SS * DD));
        atomicAdd(&out[b * CC + tid], scale * colsum[tid]);
    }
}

// ---------------------------------------------------------------------------
// kernel_launch
// inputs: 0 patch (64,576,768) f32 | 1 class_token (64,768) | 2 attn_w (200,768)
//         3 attn_b (200) | 4 gc_w (200,768) | 5 gc_b (200) | 6 lam (1)
// out: (64,200) f32
// ---------------------------------------------------------------------------
extern "C" void kernel_launch(void* const* d_in, const int* in_sizes, int n_in,
                              void* d_out, int out_size) {
    (void)in_sizes; (void)n_in; (void)out_size;
    const float* patch = (const float*)d_in[0];
    const float* ct    = (const float*)d_in[1];
    const float* aw    = (const float*)d_in[2];
    const float* ab    = (const float*)d_in[3];
    const float* gw    = (const float*)d_in[4];
    const float* gb    = (const float*)d_in[5];
    const float* lam   = (const float*)d_in[6];
    float* out = (float*)d_out;

    cudaFuncSetAttribute(attn_kernel, cudaFuncAttributeMaxDynamicSharedMemorySize,
                         SMEM_TOTAL);

    prep_kernel<<<78 + 1600, 256>>>(aw, ct, gw, gb, out);
    attn_kernel<<<dim3((SS + MT - 1) / MT, BB), 256, SMEM_TOTAL>>>(patch, ab, lam, out);
}

// round 13
// speedup vs baseline: 1.0246x; 1.0246x over previous
#include <cuda_runtime.h>
#include <cuda_fp16.h>
#include <cstdint>

#define BB 64
#define SS 576
#define DD 768
#define CC 200
#define NP 208             // padded class dim
#define MT 64              // s-rows per CTA (576 = 9*64, exact)
#define KC 32              // K chunk (elems)
#define NK 24              // 768/32
#define NSB 3              // B stages

#define AH_STRIDE 40       // f16 elems per A row (80 B: 16B-aligned STS + LDSM conflict-free)
#define BH_STRIDE 40       // f16 elems per B row (80 B, LDSM conflict-free)

#define SZ_AH    (MT * AH_STRIDE * 2)                   // 5120 per stage
#define SZ_BSTG  (NP * BH_STRIDE * 2)                   // 16640 per stage
#define OFF_AH   0
#define OFF_BH   (2 * SZ_AH)                            // 10240
#define OFF_RS   (OFF_BH + NSB * SZ_BSTG)               // 60160
#define OFF_CS   (OFF_RS + MT * 4)                      // 60416
#define SMEM_TOTAL (OFF_CS + NP * 4)                    // 61248  -> 3 CTAs/SM

// fp16 copy of attn_w, zero-padded to NP rows (static scratch, no allocs)
__device__ __half g_whf[NP * DD];

__device__ __forceinline__ uint32_t smem_u32(const void* p) {
    uint32_t a;
    asm("{ .reg .u64 t; cvta.to.shared.u64 t, %1; cvt.u32.u64 %0, t; }" : "=r"(a) : "l"(p));
    return a;
}
__device__ __forceinline__ void cp_async16(uint32_t dst, const void* src) {
    asm volatile("{ .reg .u64 g; cvta.to.global.u64 g, %1; cp.async.cg.shared.global [%0], [g], 16; }"
                 :: "r"(dst), "l"(src) : "memory");
}
#define CP_COMMIT() asm volatile("cp.async.commit_group;" ::: "memory")
#define CP_WAIT1()  asm volatile("cp.async.wait_group 1;" ::: "memory")

#define LDSM4(r0, r1, r2, r3, addr)                                           \
    asm volatile("ldmatrix.sync.aligned.m8n8.x4.shared.b16 {%0,%1,%2,%3}, [%4];" \
        : "=r"(r0), "=r"(r1), "=r"(r2), "=r"(r3) : "r"(addr))
#define LDSM2(r0, r1, addr)                                                   \
    asm volatile("ldmatrix.sync.aligned.m8n8.x2.shared.b16 {%0,%1}, [%2];"    \
        : "=r"(r0), "=r"(r1) : "r"(addr))

#define MMA16(c0, c1, a0, a1, a2, a3, b0, b1)                                 \
    asm volatile("mma.sync.aligned.m16n8k16.row.col.f16.f16.f16.f16 "         \
        "{%0,%1},{%2,%3,%4,%5},{%6,%7},{%0,%1};"                              \
        : "+r"(c0), "+r"(c1)                                                  \
        : "r"(a0), "r"(a1), "r"(a2), "r"(a3), "r"(b0), "r"(b1))

__device__ __forceinline__ float sigf(float x) { return 1.f / (1.f + __expf(-x)); }

// ---------------------------------------------------------------------------
// prep kernel: blocks [0,78): convert attn_w -> g_whf (f16, zero-padded rows)
//              blocks [78,1678): global_scores = class_token @ gc_w^T + gc_b
// ---------------------------------------------------------------------------
__global__ void prep_kernel(const float* __restrict__ aw,
                            const float* __restrict__ ct,
                            const float* __restrict__ gcw,
                            const float* __restrict__ gcb,
                            float* __restrict__ out) {
    int bid = blockIdx.x;
    if (bid < 78) {
        int base = bid * 2048 + threadIdx.x * 8;   // 78*2048 = NP*DD
        #pragma unroll
        for (int i = 0; i < 8; ++i) {
            int idx = base + i;
            int c = idx / DD;
            float v = (c < CC) ? aw[idx] : 0.f;
            g_whf[idx] = __float2half(v);
        }
    } else {
        int W = (bid - 78) * 8 + (threadIdx.x >> 5);   // 0..12799
        int lane = threadIdx.x & 31;
        int b = W & 63;
        int c = W >> 6;                                // 0..199
        const float* x = ct + (size_t)b * DD;
        const float* w = gcw + (size_t)c * DD;
        float acc = 0.f;
        #pragma unroll 4
        for (int d = lane; d < DD; d += 32) acc += x[d] * w[d];
        #pragma unroll
        for (int m = 16; m; m >>= 1) acc += __shfl_xor_sync(0xffffffffu, acc, m);
        if (lane == 0) out[b * CC + c] = acc + gcb[c];
    }
}

// ---------------------------------------------------------------------------
// attn kernel: fused logits = patch @ attn_w^T (f16 mma.sync),
//   out[b,c] += lam/(S*D) * sum_s sigmoid(logit + bias) * rowsum[b,s]
// CTA tile M=64 x N=208; warps 4(m) x 2(n); warp tile 16 x 104 (f16 acc).
// A: LDG f32 -> regs (1 iter ahead) -> convert -> STS f16 (double buffer).
// B: cp.async f16 (pre-converted), 3-stage ring. ONE barrier per iteration.
// ---------------------------------------------------------------------------
__global__ void __launch_bounds__(256, 3)
attn_kernel(const float* __restrict__ patch,
            const float* __restrict__ attn_b,
            const float* __restrict__ lam,
            float* __restrict__ out) {
    extern __shared__ __align__(16) char smem[];
    __half* Ah = (__half*)(smem + OFF_AH);
    float*  rs = (float*)(smem + OFF_RS);
    float*  colsum = (float*)(smem + OFF_CS);
    const uint32_t sb = smem_u32(smem);

    const int tid  = threadIdx.x;
    const int lane = tid & 31;
    const int warp = tid >> 5;
    const int wm   = warp >> 1;          // 0..3
    const int wn   = warp & 1;           // 0..1
    const int g    = lane >> 2;          // 0..7
    const int q    = lane & 3;           // 0..3

    const int b  = blockIdx.y;
    const int s0 = blockIdx.x * MT;

    if (tid < NP) colsum[tid] = 0.f;

    // A LDG mapping: 4 threads per row, 8 f32 each
    const int arow = tid >> 2;           // 0..63
    const int aseg = tid & 3;            // cols aseg*8 .. +7
    const float* gA = patch + ((size_t)b * SS + s0 + arow) * DD + aseg * 8;

    // ldmatrix per-lane byte offsets (conflict-free via 80B row strides)
    const uint32_t aoff = (uint32_t)(((lane & 7) + ((lane >> 3) & 1) * 8) * (AH_STRIDE * 2)
                                     + ((lane >> 4) & 1) * 16);
    const uint32_t boff = (uint32_t)(((lane & 7) + ((lane >> 4) & 1) * 8) * (BH_STRIDE * 2)
                                     + ((lane >> 3) & 1) * 16);

    uint32_t acc[13][2];
    #pragma unroll
    for (int j = 0; j < 13; ++j) { acc[j][0] = 0u; acc[j][1] = 0u; }
    float rsum = 0.f;

    auto issueB = [&](int kt) {
        uint32_t bdst = sb + OFF_BH + (kt % NSB) * SZ_BSTG;
        #pragma unroll
        for (int i = 0; i < 4; ++i) {                   // 832 chunks of 16B
            int f = tid + 256 * i;
            if (f < NP * 4) {
                int row = f >> 2, cc = f & 3;
                cp_async16(bdst + row * (BH_STRIDE * 2) + cc * 16,
                           g_whf + (size_t)row * DD + kt * KC + cc * 8);
            }
        }
        CP_COMMIT();
    };

    // prologue: B[0], B[1] in flight; A[0] in registers
    issueB(0);
    issueB(1);
    float4 r0 = *reinterpret_cast<const float4*>(gA);
    float4 r1 = *reinterpret_cast<const float4*>(gA + 4);

    for (int kt = 0; kt < NK; ++kt) {
        // ---- convert regs -> Ah[kt&1] + rowsum (no smem round trip) ----
        {
            rsum += (r0.x + r0.y) + (r0.z + r0.w) + (r1.x + r1.y) + (r1.z + r1.w);
            __half2 h0 = __floats2half2_rn(r0.x, r0.y);
            __half2 h1 = __floats2half2_rn(r0.z, r0.w);
            __half2 h2 = __floats2half2_rn(r1.x, r1.y);
            __half2 h3 = __floats2half2_rn(r1.z, r1.w);
            uint4 u;
            u.x = *reinterpret_cast<uint32_t*>(&h0);
            u.y = *reinterpret_cast<uint32_t*>(&h1);
            u.z = *reinterpret_cast<uint32_t*>(&h2);
            u.w = *reinterpret_cast<uint32_t*>(&h3);
            *reinterpret_cast<uint4*>(Ah + (kt & 1) * (MT * AH_STRIDE)
                                      + arow * AH_STRIDE + aseg * 8) = u;   // 80B rows: aligned
        }
        // ---- prefetch A[kt+1] into registers ----
        if (kt + 1 < NK) {
            const float* p = gA + (kt + 1) * KC;
            r0 = *reinterpret_cast<const float4*>(p);
            r1 = *reinterpret_cast<const float4*>(p + 4);
        }

        CP_WAIT1();                      // B[kt] arrived (pending <= {B[kt+1]})
        __syncthreads();                 // Ah[kt&1] visible; B slot reuse safe

        if (kt + 2 < NK) issueB(kt + 2); else CP_COMMIT();

        // ---- mma: 2 k16 halves x 13 nfrags ----
        const uint32_t abase = sb + OFF_AH + (kt & 1) * SZ_AH
                             + wm * 16 * (AH_STRIDE * 2) + aoff;
        const uint32_t bstage = sb + OFF_BH + (kt % NSB) * SZ_BSTG
                              + wn * 104 * (BH_STRIDE * 2) + boff;
        #pragma unroll
        for (int h = 0; h < 2; ++h) {
            uint32_t a0, a1, a2, a3;
            LDSM4(a0, a1, a2, a3, abase + h * 32);
            #pragma unroll
            for (int p = 0; p < 6; ++p) {
                uint32_t b0, b1, b2, b3;
                LDSM4(b0, b1, b2, b3, bstage + p * 16 * (BH_STRIDE * 2) + h * 32);
                MMA16(acc[2 * p][0],     acc[2 * p][1],     a0, a1, a2, a3, b0, b1);
                MMA16(acc[2 * p + 1][0], acc[2 * p + 1][1], a0, a1, a2, a3, b2, b3);
            }
            uint32_t b0, b1;
            LDSM2(b0, b1, bstage + 96 * (BH_STRIDE * 2) + h * 32);
            MMA16(acc[12][0], acc[12][1], a0, a1, a2, a3, b0, b1);
        }
    }

    // ---- rowsum reduce over the 4 threads per row ----
    rsum += __shfl_xor_sync(0xffffffffu, rsum, 1);
    rsum += __shfl_xor_sync(0xffffffffu, rsum, 2);
    if ((tid & 3) == 0) rs[arow] = rsum;
    __syncthreads();

    // ---- epilogue: sigmoid(logit + bias) * rowsum, reduce over s ----
    const float rlo = rs[wm * 16 + g];
    const float rhi = rs[wm * 16 + g + 8];
    #pragma unroll
    for (int j = 0; j < 13; ++j) {
        const int ce = wn * 104 + j * 8 + 2 * q;
        float be = (ce     < CC) ? __ldg(&attn_b[ce])     : 0.f;
        float bo = (ce + 1 < CC) ? __ldg(&attn_b[ce + 1]) : 0.f;
        float2 c0 = __half22float2(*reinterpret_cast<__half2*>(&acc[j][0]));  // rows g
        float2 c1 = __half22float2(*reinterpret_cast<__half2*>(&acc[j][1]));  // rows g+8
        float pe = sigf(c0.x + be) * rlo + sigf(c1.x + be) * rhi;
        float po = sigf(c0.y + bo) * rlo + sigf(c1.y + bo) * rhi;
        #pragma unroll
        for (int m = 4; m < 32; m <<= 1) {
            pe += __shfl_xor_sync(0xffffffffu, pe, m);
            po += __shfl_xor_sync(0xffffffffu, po, m);
        }
        if (lane < 4) {                  // lane == q
            atomicAdd(&colsum[ce],     pe);
            atomicAdd(&colsum[ce + 1], po);
        }
    }
    __syncthreads();

    if (tid < CC) {
        float scale = __ldg(&lam[0]) * (1.f / (float)(SS * DD));
        atomicAdd(&out[b * CC + tid], scale * colsum[tid]);
    }
}

// ---------------------------------------------------------------------------
// kernel_launch
// inputs: 0 patch (64,576,768) f32 | 1 class_token (64,768) | 2 attn_w (200,768)
//         3 attn_b (200) | 4 gc_w (200,768) | 5 gc_b (200) | 6 lam (1)
// out: (64,200) f32
// ---------------------------------------------------------------------------
extern "C" void kernel_launch(void* const* d_in, const int* in_sizes, int n_in,
                              void* d_out, int out_size) {
    (void)in_sizes; (void)n_in; (void)out_size;
    const float* patch = (const float*)d_in[0];
    const float* ct    = (const float*)d_in[1];
    const float* aw    = (const float*)d_in[2];
    const float* ab    = (const float*)d_in[3];
    const float* gw    = (const float*)d_in[4];
    const float* gb    = (const float*)d_in[5];
    const float* lam   = (const float*)d_in[6];
    float* out = (float*)d_out;

    cudaFuncSetAttribute(attn_kernel, cudaFuncAttributeMaxDynamicSharedMemorySize,
                         SMEM_TOTAL);

    prep_kernel<<<78 + 1600, 256>>>(aw, ct, gw, gb, out);
    attn_kernel<<<dim3(SS / MT, BB), 256, SMEM_TOTAL>>>(patch, ab, lam, out);
}